// round 13
// baseline (speedup 1.0000x reference)
#include <cuda_runtime.h>
#include <cuda_fp16.h>
#include <cstdint>
#include <math.h>

// ============================================================================
// Problem constants
// ============================================================================
#define DIM   512
#define S_LEN 4096
#define NBAT  4
#define ROWS  (NBAT * S_LEN)      // 16384

// GEMM tiling: BM=128, BN=128, BK=32, 256 threads (8 warps 4x2, 32x64 warp tile)
#define BM 128
#define BN 128
#define BK 32
#define THREADS 256
#define STAGES 4
// stage layout: A 8KB | B 8KB = 16KB
#define ST_A 0
#define ST_B 8192
#define STB  16384
#define SMEM_DYN (STAGES * STB)   // 65536

// ============================================================================
// PTX helpers (plain sm_103-legal: cp.async / ldmatrix / mma.sync only)
// ============================================================================
__device__ __forceinline__ uint32_t smem_to_u32(const void* p) {
    uint32_t a;
    asm("{ .reg .u64 t; cvta.to.shared.u64 t, %1; cvt.u32.u64 %0, t; }" : "=r"(a) : "l"(p));
    return a;
}
#define CP_A16(s, g) \
    asm volatile("cp.async.cg.shared.global [%0], [%1], 16;" :: "r"(s), "l"(g))
#define CP_COMMIT() asm volatile("cp.async.commit_group;" ::: "memory")
#define CP_WAIT(n)  asm volatile("cp.async.wait_group %0;" :: "n"(n) : "memory")

__device__ __forceinline__ void ldm_x4(uint32_t* r, uint32_t addr) {
    asm volatile("ldmatrix.sync.aligned.m8n8.x4.shared.b16 {%0,%1,%2,%3}, [%4];"
        : "=r"(r[0]), "=r"(r[1]), "=r"(r[2]), "=r"(r[3]) : "r"(addr));
}
__device__ __forceinline__ void ldm_x4_t(uint32_t* r, uint32_t addr) {
    asm volatile("ldmatrix.sync.aligned.m8n8.x4.trans.shared.b16 {%0,%1,%2,%3}, [%4];"
        : "=r"(r[0]), "=r"(r[1]), "=r"(r[2]), "=r"(r[3]) : "r"(addr));
}
__device__ __forceinline__ void mma_f16(float* d, const uint32_t* a, const uint32_t* b) {
    asm volatile("mma.sync.aligned.m16n8k16.row.col.f32.f16.f16.f32 "
        "{%0,%1,%2,%3}, {%4,%5,%6,%7}, {%8,%9}, {%0,%1,%2,%3};"
        : "+f"(d[0]), "+f"(d[1]), "+f"(d[2]), "+f"(d[3])
        : "r"(a[0]), "r"(a[1]), "r"(a[2]), "r"(a[3]), "r"(b[0]), "r"(b[1]));
}

// ============================================================================
// Scratch buffers
// ============================================================================
__device__ __align__(128) __half g_norms[(size_t)ROWS * DIM];
__device__ __align__(128) __half g_Q[(size_t)ROWS * DIM];
__device__ __align__(128) __half g_K[(size_t)ROWS * DIM];
__device__ __align__(128) __half g_V[(size_t)ROWS * DIM];
__device__ __align__(128) __half g_E[(size_t)NBAT * S_LEN * S_LEN];   // exp(scores), fp16
__device__ __align__(128) __half g_X[(size_t)ROWS * DIM];
__device__ __align__(128) __half g_W[(size_t)6 * DIM * DIM];
__device__ __align__(128) float g_XO[(size_t)ROWS * DIM];

// ============================================================================
// Input LayerNorm -> fp16 norms
// ============================================================================
__global__ void __launch_bounds__(128) ln_in_kernel(
    const float* __restrict__ text, const float* __restrict__ img,
    const float* __restrict__ gt, const float* __restrict__ bt,
    const float* __restrict__ gi, const float* __restrict__ bi,
    __half* __restrict__ outH)
{
    int row = blockIdx.x;
    const float *src, *g, *b;
    if (row < 2 * S_LEN) { src = text + (size_t)row * DIM;              g = gt; b = bt; }
    else                 { src = img  + (size_t)(row - 2*S_LEN) * DIM;  g = gi; b = bi; }

    int t = threadIdx.x;
    float4 x = ((const float4*)src)[t];
    float s  = x.x + x.y + x.z + x.w;
    float ss = x.x*x.x + x.y*x.y + x.z*x.z + x.w*x.w;

    __shared__ float rs[4], rss[4];
    #pragma unroll
    for (int o = 16; o > 0; o >>= 1) {
        s  += __shfl_xor_sync(0xffffffffu, s,  o);
        ss += __shfl_xor_sync(0xffffffffu, ss, o);
    }
    if ((t & 31) == 0) { rs[t>>5] = s; rss[t>>5] = ss; }
    __syncthreads();
    s  = rs[0] + rs[1] + rs[2] + rs[3];
    ss = rss[0] + rss[1] + rss[2] + rss[3];

    float mu  = s * (1.0f / DIM);
    float var = ss * (1.0f / DIM) - mu * mu;
    float inv = rsqrtf(var + 1e-5f);

    float4 gg = ((const float4*)g)[t];
    float4 bb = ((const float4*)b)[t];
    float v0 = (x.x - mu) * inv * gg.x + bb.x;
    float v1 = (x.y - mu) * inv * gg.y + bb.y;
    float v2 = (x.z - mu) * inv * gg.z + bb.z;
    float v3 = (x.w - mu) * inv * gg.w + bb.w;

    size_t base = (size_t)row * DIM + t * 4;
    ((__half2*)(outH + base))[0] = __halves2half2(__float2half(v0), __float2half(v1));
    ((__half2*)(outH + base))[1] = __halves2half2(__float2half(v2), __float2half(v3));
}

// ============================================================================
// Convert 6 weight matrices to fp16
// ============================================================================
__global__ void __launch_bounds__(256) convert_weights_kernel(
    const float* __restrict__ w0, const float* __restrict__ w1,
    const float* __restrict__ w2, const float* __restrict__ w3,
    const float* __restrict__ w4, const float* __restrict__ w5,
    __half* __restrict__ W)
{
    int mat = blockIdx.y;
    const float* ws[6] = {w0, w1, w2, w3, w4, w5};
    const float* w = ws[mat];
    int i = blockIdx.x * 256 + threadIdx.x;
    W[(size_t)mat * DIM * DIM + i] = __float2half(w[i]);
}

// ============================================================================
// Final dual LayerNorm: one block per XO row, writes BOTH ln_t and ln_i rows
// ============================================================================
__global__ void __launch_bounds__(128) ln_out_dual_kernel(
    const float* __restrict__ x,
    const float* __restrict__ gt, const float* __restrict__ bt,
    const float* __restrict__ gi, const float* __restrict__ bi,
    float* __restrict__ out)
{
    int row = blockIdx.x;
    const float* src = x + (size_t)row * DIM;

    int t = threadIdx.x;
    float4 v = ((const float4*)src)[t];
    float s  = v.x + v.y + v.z + v.w;
    float ss = v.x*v.x + v.y*v.y + v.z*v.z + v.w*v.w;

    __shared__ float rs[4], rss[4];
    #pragma unroll
    for (int o = 16; o > 0; o >>= 1) {
        s  += __shfl_xor_sync(0xffffffffu, s,  o);
        ss += __shfl_xor_sync(0xffffffffu, ss, o);
    }
    if ((t & 31) == 0) { rs[t>>5] = s; rss[t>>5] = ss; }
    __syncthreads();
    s  = rs[0] + rs[1] + rs[2] + rs[3];
    ss = rss[0] + rss[1] + rss[2] + rss[3];

    float mu  = s * (1.0f / DIM);
    float var = ss * (1.0f / DIM) - mu * mu;
    float inv = rsqrtf(var + 1e-5f);

    float nx = (v.x - mu) * inv;
    float ny = (v.y - mu) * inv;
    float nz = (v.z - mu) * inv;
    float nw = (v.w - mu) * inv;

    float4 g1 = ((const float4*)gt)[t];
    float4 b1 = ((const float4*)bt)[t];
    float4 o1;
    o1.x = nx * g1.x + b1.x; o1.y = ny * g1.y + b1.y;
    o1.z = nz * g1.z + b1.z; o1.w = nw * g1.w + b1.w;
    ((float4*)(out + (size_t)row * DIM))[t] = o1;

    float4 g2 = ((const float4*)gi)[t];
    float4 b2 = ((const float4*)bi)[t];
    float4 o2;
    o2.x = nx * g2.x + b2.x; o2.y = ny * g2.y + b2.y;
    o2.z = nz * g2.z + b2.z; o2.w = nw * g2.w + b2.w;
    ((float4*)(out + ((size_t)(row + ROWS)) * DIM))[t] = o2;
}

// ============================================================================
// Shared GEMM core: mma.sync fp16 single-pass (BM=128, BN=128, BK=32, 256 thr)
// 8 warps in 4x2 grid, 32x64 warp tile: 16 mma per 6 ldmatrix.
// LAYOUT 0 (NT): B = [N,K] k-contiguous
// LAYOUT 1 (NN): B = [K,N] n-contiguous (ldmatrix.trans)
// EPI 0: fp32 C (alpha + bias)                      [Wo -> XO]
// EPI 1: fp16 C (alpha + bias)                      [projections]
// EPI 2: fp16 C = exp(min(alpha*acc,11))            [scores -> E]
// EPI 3: fp16 C = acc / rowsum(A)   (self-normalizing PV; rowsum from smem A)
// ============================================================================
template<int LAYOUT, int EPI>
__device__ __forceinline__ void gemm_core(
    const __half* __restrict__ A, const __half* __restrict__ B,
    const float* __restrict__ bias,
    float* __restrict__ Cf, __half* __restrict__ CH,
    int N, int K, float alpha, int m0, int n0, char* smemc)
{
    uint32_t base = smem_to_u32(smemc);
    int tid = threadIdx.x, wid = tid >> 5, lane = tid & 31;
    int NK = K / BK;

    auto load_stage = [&](int kt) {
        uint32_t sb = base + (uint32_t)(kt & (STAGES - 1)) * STB;
        int kb = kt * BK;
        // A: 128 rows x 64B, SW64 swizzle. 512 slots, 2 per thread.
        #pragma unroll
        for (int i = 0; i < 2; i++) {
            int slot = tid + i * THREADS;
            int row = slot >> 2, unit = slot & 3;
            uint32_t off = (uint32_t)(row * 64 + unit * 16);
            off ^= (off >> 3) & 0x30;
            CP_A16(sb + ST_A + off, A + (size_t)(m0 + row) * K + kb + unit * 8);
        }
        if (LAYOUT == 0) {
            // B NT: 128 rows x 64B. 512 slots, 2 per thread.
            #pragma unroll
            for (int i = 0; i < 2; i++) {
                int slot = tid + i * THREADS;
                int row = slot >> 2, unit = slot & 3;
                uint32_t off = (uint32_t)(row * 64 + unit * 16);
                off ^= (off >> 3) & 0x30;
                CP_A16(sb + ST_B + off, B + (size_t)(n0 + row) * K + kb + unit * 8);
            }
        } else {
            // B NN: 32 k-rows x 256B (BN=128). 512 slots, 2 per thread.
            #pragma unroll
            for (int i = 0; i < 2; i++) {
                int slot = tid + i * THREADS;
                int row = slot >> 4, unit = slot & 15;
                uint32_t off = (uint32_t)(row * 256 + unit * 16);
                off ^= (off >> 4) & 0x70;
                CP_A16(sb + ST_B + off, B + (size_t)(kb + row) * N + n0 + unit * 8);
            }
        }
    };

    load_stage(0); CP_COMMIT();
    load_stage(1); CP_COMMIT();
    load_stage(2); CP_COMMIT();

    int wm = wid & 3, wn = wid >> 2;     // 4x2 warp grid, 32x64 warp tile
    float acc[2][8][4];
    #pragma unroll
    for (int a = 0; a < 2; a++)
        #pragma unroll
        for (int b = 0; b < 8; b++)
            #pragma unroll
            for (int c = 0; c < 4; c++) acc[a][b][c] = 0.0f;

    float psum = 0.0f;   // EPI 3: partial row sum of A (this thread's slice)

    for (int kt = 0; kt < NK; kt++) {
        if (kt + 3 < NK)      { load_stage(kt + 3); CP_COMMIT(); CP_WAIT(3); }
        else if (kt + 2 < NK) { CP_WAIT(2); }
        else if (kt + 1 < NK) { CP_WAIT(1); }
        else                  { CP_WAIT(0); }
        __syncthreads();

        uint32_t sb = base + (uint32_t)(kt & (STAGES - 1)) * STB;

        #pragma unroll
        for (int ks = 0; ks < 2; ks++) {
            int k0 = ks * 16;

            uint32_t ar[2][4];
            #pragma unroll
            for (int mt = 0; mt < 2; mt++) {
                int row = wm * 32 + mt * 16 + (lane & 15);
                uint32_t off = (uint32_t)(row * 64 + k0 * 2 + ((lane >> 4) << 4));
                off ^= (off >> 3) & 0x30;
                ldm_x4(ar[mt], sb + ST_A + off);
            }

            uint32_t br[8][2];
            if (LAYOUT == 0) {
                #pragma unroll
                for (int p = 0; p < 4; p++) {
                    int nrow = wn * 64 + p * 16 + (lane & 7) + 8 * ((lane >> 4) & 1);
                    uint32_t off = (uint32_t)(nrow * 64 + k0 * 2 + ((lane >> 3) & 1) * 16);
                    off ^= (off >> 3) & 0x30;
                    uint32_t r[4];
                    ldm_x4(r, sb + ST_B + off);
                    br[p*2][0] = r[0]; br[p*2][1] = r[1];
                    br[p*2+1][0] = r[2]; br[p*2+1][1] = r[3];
                }
            } else {
                #pragma unroll
                for (int p = 0; p < 4; p++) {
                    int krow = k0 + (lane & 7) + 8 * ((lane >> 3) & 1);
                    int ncol = wn * 64 + p * 16 + 8 * (lane >> 4);
                    uint32_t off = (uint32_t)(krow * 256 + ncol * 2);
                    off ^= (off >> 4) & 0x70;
                    uint32_t r[4];
                    ldm_x4_t(r, sb + ST_B + off);
                    br[p*2][0] = r[0]; br[p*2][1] = r[1];
                    br[p*2+1][0] = r[2]; br[p*2+1][1] = r[3];
                }
            }

            #pragma unroll
            for (int mt = 0; mt < 2; mt++)
                #pragma unroll
                for (int nt = 0; nt < 8; nt++)
                    mma_f16(acc[mt][nt], ar[mt], br[nt]);
        }

        if (EPI == 3) {
            // Accumulate row sums of the A tile (thread pair per row: 2x16B each).
            uint32_t sboff = (uint32_t)(kt & (STAGES - 1)) * STB + ST_A;
            int row = tid >> 1;
            #pragma unroll
            for (int u = 0; u < 2; u++) {
                uint32_t off = (uint32_t)(row * 64 + ((tid & 1) * 2 + u) * 16);
                off ^= (off >> 3) & 0x30;
                uint4 v = *(const uint4*)(smemc + sboff + off);
                const __half2* h = (const __half2*)&v;
                #pragma unroll
                for (int j = 0; j < 4; j++) {
                    float2 f = __half22float2(h[j]);
                    psum += f.x + f.y;
                }
            }
        }
        __syncthreads();
    }

    // ---------------- epilogue ----------------
    float* rowsumSm = (float*)smemc;   // EPI 3 only; pipeline smem is free now
    if (EPI == 3) {
        psum += __shfl_xor_sync(0xffffffffu, psum, 1);
        if ((tid & 1) == 0) rowsumSm[tid >> 1] = psum;
        __syncthreads();
    }

    #pragma unroll
    for (int mt = 0; mt < 2; mt++) {
        int lr   = wm * 32 + mt * 16 + (lane >> 2);   // local row in [0,128)
        int mrow = m0 + lr;
        float rs0 = 1.0f, rs1 = 1.0f;
        if (EPI == 3) {
            rs0 = 1.0f / rowsumSm[lr];
            rs1 = 1.0f / rowsumSm[lr + 8];
        }
        #pragma unroll
        for (int nt = 0; nt < 8; nt++) {
            int n = n0 + wn * 64 + nt * 8 + (lane & 3) * 2;
            float c0, c1, c2, c3;
            if (EPI == 0 || EPI == 1) {
                float b0 = bias ? __ldg(&bias[n])     : 0.0f;
                float b1 = bias ? __ldg(&bias[n + 1]) : 0.0f;
                c0 = alpha * acc[mt][nt][0] + b0;
                c1 = alpha * acc[mt][nt][1] + b1;
                c2 = alpha * acc[mt][nt][2] + b0;
                c3 = alpha * acc[mt][nt][3] + b1;
            } else if (EPI == 2) {
                c0 = __expf(fminf(alpha * acc[mt][nt][0], 11.0f));
                c1 = __expf(fminf(alpha * acc[mt][nt][1], 11.0f));
                c2 = __expf(fminf(alpha * acc[mt][nt][2], 11.0f));
                c3 = __expf(fminf(alpha * acc[mt][nt][3], 11.0f));
            } else {  // EPI == 3
                c0 = acc[mt][nt][0] * rs0;
                c1 = acc[mt][nt][1] * rs0;
                c2 = acc[mt][nt][2] * rs1;
                c3 = acc[mt][nt][3] * rs1;
            }
            size_t o0 = (size_t)mrow * N + n;
            size_t o1 = (size_t)(mrow + 8) * N + n;
            if (EPI == 0) {
                *(float2*)(Cf + o0) = make_float2(c0, c1);
                *(float2*)(Cf + o1) = make_float2(c2, c3);
            } else {
                *(__half2*)(CH + o0) = __halves2half2(__float2half(c0), __float2half(c1));
                *(__half2*)(CH + o1) = __halves2half2(__float2half(c2), __float2half(c3));
            }
        }
    }
}

// Generic batched wrapper
template<int LAYOUT, int EPI>
__global__ void __launch_bounds__(THREADS, 2) mma_gemm_kernel(
    const __half* __restrict__ A, const __half* __restrict__ B,
    const float* __restrict__ bias,
    float* __restrict__ Cf, __half* __restrict__ CH,
    int N, int K, float alpha,
    long long sA, long long sB, long long sC)
{
    extern __shared__ char smem[];
    int z = blockIdx.z;
    gemm_core<LAYOUT, EPI>(
        A + (size_t)z * sA, B + (size_t)z * sB, bias,
        Cf ? Cf + (size_t)z * sC : nullptr,
        CH ? CH + (size_t)z * sC : nullptr,
        N, K, alpha, blockIdx.y * BM, blockIdx.x * BN, smem);
}

// Merged projection kernel: Q, Kt, Ki, Vt, Vi in one launch.
// grid = (4, 384): y<128 Q | y<192 Kt | y<256 Ki | y<320 Vt | y<384 Vi
__global__ void __launch_bounds__(THREADS, 2) proj_kernel(
    const __half* __restrict__ NORM, const __half* __restrict__ W,
    const float* __restrict__ bq, const float* __restrict__ bkt,
    const float* __restrict__ bki, const float* __restrict__ bvt,
    const float* __restrict__ bvi,
    __half* __restrict__ Q, __half* __restrict__ K, __half* __restrict__ V)
{
    extern __shared__ char smem[];
    const size_t WSZ = (size_t)DIM * DIM;
    int y = blockIdx.y;
    int mat, arow;
    __half* outp;
    const float* bias;
    if (y < 128)      { mat = 0; arow = y * 128;                outp = Q; bias = bq; }
    else if (y < 192) { mat = 1; arow = (y - 128) * 128;        outp = K; bias = bkt; }
    else if (y < 256) { mat = 3; arow = 8192 + (y - 192) * 128; outp = K; bias = bki; }
    else if (y < 320) { mat = 2; arow = (y - 256) * 128;        outp = V; bias = bvt; }
    else              { mat = 4; arow = 8192 + (y - 320) * 128; outp = V; bias = bvi; }

    gemm_core<0, 1>(
        NORM + (size_t)arow * DIM, W + (size_t)mat * WSZ, bias,
        nullptr, outp + (size_t)arow * DIM,
        DIM, DIM, 1.0f, 0, blockIdx.x * BN, smem);
}

// ============================================================================
// Host orchestration
// ============================================================================
extern "C" void kernel_launch(void* const* d_in, const int* in_sizes, int n_in,
                              void* d_out, int out_size)
{
    const float* text  = (const float*)d_in[0];
    const float* img   = (const float*)d_in[1];
    const float* ln_tg = (const float*)d_in[2];
    const float* ln_tb = (const float*)d_in[3];
    const float* ln_ig = (const float*)d_in[4];
    const float* ln_ib = (const float*)d_in[5];
    const float* Wq  = (const float*)d_in[6];  const float* bq  = (const float*)d_in[7];
    const float* Wkt = (const float*)d_in[8];  const float* bkt = (const float*)d_in[9];
    const float* Wvt = (const float*)d_in[10]; const float* bvt = (const float*)d_in[11];
    const float* Wki = (const float*)d_in[12]; const float* bki = (const float*)d_in[13];
    const float* Wvi = (const float*)d_in[14]; const float* bvi = (const float*)d_in[15];
    const float* Wo  = (const float*)d_in[16]; const float* bo  = (const float*)d_in[17];
    float* out = (float*)d_out;

    static bool attr_done = false;
    if (!attr_done) {
        cudaFuncSetAttribute(proj_kernel,          cudaFuncAttributeMaxDynamicSharedMemorySize, SMEM_DYN);
        cudaFuncSetAttribute(mma_gemm_kernel<0,0>, cudaFuncAttributeMaxDynamicSharedMemorySize, SMEM_DYN);
        cudaFuncSetAttribute(mma_gemm_kernel<0,2>, cudaFuncAttributeMaxDynamicSharedMemorySize, SMEM_DYN);
        cudaFuncSetAttribute(mma_gemm_kernel<1,3>, cudaFuncAttributeMaxDynamicSharedMemorySize, SMEM_DYN);
        attr_done = true;
    }

    void *pN, *pQ, *pK, *pV, *pE, *pX, *pW, *pXO;
    cudaGetSymbolAddress(&pN, g_norms);
    cudaGetSymbolAddress(&pQ, g_Q); cudaGetSymbolAddress(&pK, g_K); cudaGetSymbolAddress(&pV, g_V);
    cudaGetSymbolAddress(&pE, g_E); cudaGetSymbolAddress(&pX, g_X);
    cudaGetSymbolAddress(&pW, g_W); cudaGetSymbolAddress(&pXO, g_XO);

    __half* NORM = (__half*)pN;
    __half* Q = (__half*)pQ; __half* K = (__half*)pK; __half* V = (__half*)pV;
    __half* E = (__half*)pE; __half* X = (__half*)pX;
    __half* W = (__half*)pW;
    float* XO = (float*)pXO;

    const float scale = 0.04419417382415922f;  // 512^-0.5
    const size_t WSZ = (size_t)DIM * DIM;      // 262144

    // 1) input LN -> fp16 norms
    ln_in_kernel<<<ROWS, 128>>>(text, img, ln_tg, ln_tb, ln_ig, ln_ib, NORM);

    // 2) convert weights (order: q, kt, vt, ki, vi, o)
    convert_weights_kernel<<<dim3(1024, 6), 256>>>(Wq, Wkt, Wvt, Wki, Wvi, Wo, W);

    // 3) all projections, one launch
    proj_kernel<<<dim3(4, 384), THREADS, SMEM_DYN>>>(
        NORM, W, bq, bkt, bki, bvt, bvi, Q, K, V);

    // 4) E = exp(scale * Q @ K^T) (batched NT)
    mma_gemm_kernel<0,2><<<dim3(32, 32, NBAT), THREADS, SMEM_DYN>>>(
        Q, K, nullptr, nullptr, E,
        S_LEN, DIM, scale,
        (long long)S_LEN * DIM, (long long)S_LEN * DIM, (long long)S_LEN * S_LEN);

    // 5) X = (E @ V) / rowsum(E) (batched NN, self-normalizing)
    mma_gemm_kernel<1,3><<<dim3(4, 32, NBAT), THREADS, SMEM_DYN>>>(
        E, V, nullptr, nullptr, X,
        DIM, S_LEN, 1.0f,
        (long long)S_LEN * S_LEN, (long long)S_LEN * DIM, (long long)S_LEN * DIM);

    // 6) XO = X @ Wo^T + bo (NT, fp32 out)
    mma_gemm_kernel<0,0><<<dim3(4, 128, 1), THREADS, SMEM_DYN>>>(
        X, W + 5*WSZ, bo, XO, nullptr,
        DIM, DIM, 1.0f, 0, 0, 0);

    // 7) final dual LayerNorm (one block per XO row, both outputs)
    ln_out_dual_kernel<<<ROWS, 128>>>(XO, ln_tg, ln_tb, ln_ig, ln_ib, out);
}

// round 16
// speedup vs baseline: 1.4944x; 1.4944x over previous
#include <cuda_runtime.h>
#include <cuda_fp16.h>
#include <cstdint>
#include <math.h>

// ============================================================================
// Problem constants
// ============================================================================
#define DIM   512
#define S_LEN 4096
#define NBAT  4
#define ROWS  (NBAT * S_LEN)      // 16384

// GEMM tiling: BM=128, BN=64, BK=64, 256 threads (8 warps 4x2, 32x32 warp tile)
#define BM 128
#define BN 64
#define BK 64
#define THREADS 256
#define STAGES 3
// stage layout: A 16KB | B 8KB = 24KB
#define ST_A 0
#define ST_B 16384
#define STB  24576
#define SMEM_DYN (STAGES * STB)   // 73728

// ============================================================================
// PTX helpers (plain sm_103-legal: cp.async / ldmatrix / mma.sync only)
// ============================================================================
__device__ __forceinline__ uint32_t smem_to_u32(const void* p) {
    uint32_t a;
    asm("{ .reg .u64 t; cvta.to.shared.u64 t, %1; cvt.u32.u64 %0, t; }" : "=r"(a) : "l"(p));
    return a;
}
#define CP_A16(s, g) \
    asm volatile("cp.async.cg.shared.global [%0], [%1], 16;" :: "r"(s), "l"(g))
#define CP_COMMIT() asm volatile("cp.async.commit_group;" ::: "memory")
#define CP_WAIT(n)  asm volatile("cp.async.wait_group %0;" :: "n"(n) : "memory")

__device__ __forceinline__ void ldm_x4(uint32_t* r, uint32_t addr) {
    asm volatile("ldmatrix.sync.aligned.m8n8.x4.shared.b16 {%0,%1,%2,%3}, [%4];"
        : "=r"(r[0]), "=r"(r[1]), "=r"(r[2]), "=r"(r[3]) : "r"(addr));
}
__device__ __forceinline__ void ldm_x4_t(uint32_t* r, uint32_t addr) {
    asm volatile("ldmatrix.sync.aligned.m8n8.x4.trans.shared.b16 {%0,%1,%2,%3}, [%4];"
        : "=r"(r[0]), "=r"(r[1]), "=r"(r[2]), "=r"(r[3]) : "r"(addr));
}
__device__ __forceinline__ void mma_f16(float* d, const uint32_t* a, const uint32_t* b) {
    asm volatile("mma.sync.aligned.m16n8k16.row.col.f32.f16.f16.f32 "
        "{%0,%1,%2,%3}, {%4,%5,%6,%7}, {%8,%9}, {%0,%1,%2,%3};"
        : "+f"(d[0]), "+f"(d[1]), "+f"(d[2]), "+f"(d[3])
        : "r"(a[0]), "r"(a[1]), "r"(a[2]), "r"(a[3]), "r"(b[0]), "r"(b[1]));
}

// ============================================================================
// Scratch buffers
// ============================================================================
__device__ __align__(128) __half g_norms[(size_t)ROWS * DIM];
__device__ __align__(128) __half g_Q[(size_t)ROWS * DIM];
__device__ __align__(128) __half g_K[(size_t)ROWS * DIM];
__device__ __align__(128) __half g_V[(size_t)ROWS * DIM];
__device__ __align__(128) __half g_E[(size_t)NBAT * S_LEN * S_LEN];   // exp(scores), fp16
__device__ __align__(128) __half g_X[(size_t)ROWS * DIM];
__device__ __align__(128) __half g_W[(size_t)6 * DIM * DIM];
__device__ __align__(128) float g_XO[(size_t)ROWS * DIM];

// ============================================================================
// Input LayerNorm -> fp16 norms
// ============================================================================
__global__ void __launch_bounds__(128) ln_in_kernel(
    const float* __restrict__ text, const float* __restrict__ img,
    const float* __restrict__ gt, const float* __restrict__ bt,
    const float* __restrict__ gi, const float* __restrict__ bi,
    __half* __restrict__ outH)
{
    int row = blockIdx.x;
    const float *src, *g, *b;
    if (row < 2 * S_LEN) { src = text + (size_t)row * DIM;              g = gt; b = bt; }
    else                 { src = img  + (size_t)(row - 2*S_LEN) * DIM;  g = gi; b = bi; }

    int t = threadIdx.x;
    float4 x = ((const float4*)src)[t];
    float s  = x.x + x.y + x.z + x.w;
    float ss = x.x*x.x + x.y*x.y + x.z*x.z + x.w*x.w;

    __shared__ float rs[4], rss[4];
    #pragma unroll
    for (int o = 16; o > 0; o >>= 1) {
        s  += __shfl_xor_sync(0xffffffffu, s,  o);
        ss += __shfl_xor_sync(0xffffffffu, ss, o);
    }
    if ((t & 31) == 0) { rs[t>>5] = s; rss[t>>5] = ss; }
    __syncthreads();
    s  = rs[0] + rs[1] + rs[2] + rs[3];
    ss = rss[0] + rss[1] + rss[2] + rss[3];

    float mu  = s * (1.0f / DIM);
    float var = ss * (1.0f / DIM) - mu * mu;
    float inv = rsqrtf(var + 1e-5f);

    float4 gg = ((const float4*)g)[t];
    float4 bb = ((const float4*)b)[t];
    float v0 = (x.x - mu) * inv * gg.x + bb.x;
    float v1 = (x.y - mu) * inv * gg.y + bb.y;
    float v2 = (x.z - mu) * inv * gg.z + bb.z;
    float v3 = (x.w - mu) * inv * gg.w + bb.w;

    size_t base = (size_t)row * DIM + t * 4;
    ((__half2*)(outH + base))[0] = __halves2half2(__float2half(v0), __float2half(v1));
    ((__half2*)(outH + base))[1] = __halves2half2(__float2half(v2), __float2half(v3));
}

// ============================================================================
// Convert 6 weight matrices to fp16
// ============================================================================
__global__ void __launch_bounds__(256) convert_weights_kernel(
    const float* __restrict__ w0, const float* __restrict__ w1,
    const float* __restrict__ w2, const float* __restrict__ w3,
    const float* __restrict__ w4, const float* __restrict__ w5,
    __half* __restrict__ W)
{
    int mat = blockIdx.y;
    const float* ws[6] = {w0, w1, w2, w3, w4, w5};
    const float* w = ws[mat];
    int i = blockIdx.x * 256 + threadIdx.x;
    W[(size_t)mat * DIM * DIM + i] = __float2half(w[i]);
}

// ============================================================================
// Final dual LayerNorm: one block per XO row, writes BOTH ln_t and ln_i rows
// ============================================================================
__global__ void __launch_bounds__(128) ln_out_dual_kernel(
    const float* __restrict__ x,
    const float* __restrict__ gt, const float* __restrict__ bt,
    const float* __restrict__ gi, const float* __restrict__ bi,
    float* __restrict__ out)
{
    int row = blockIdx.x;
    const float* src = x + (size_t)row * DIM;

    int t = threadIdx.x;
    float4 v = ((const float4*)src)[t];
    float s  = v.x + v.y + v.z + v.w;
    float ss = v.x*v.x + v.y*v.y + v.z*v.z + v.w*v.w;

    __shared__ float rs[4], rss[4];
    #pragma unroll
    for (int o = 16; o > 0; o >>= 1) {
        s  += __shfl_xor_sync(0xffffffffu, s,  o);
        ss += __shfl_xor_sync(0xffffffffu, ss, o);
    }
    if ((t & 31) == 0) { rs[t>>5] = s; rss[t>>5] = ss; }
    __syncthreads();
    s  = rs[0] + rs[1] + rs[2] + rs[3];
    ss = rss[0] + rss[1] + rss[2] + rss[3];

    float mu  = s * (1.0f / DIM);
    float var = ss * (1.0f / DIM) - mu * mu;
    float inv = rsqrtf(var + 1e-5f);

    float nx = (v.x - mu) * inv;
    float ny = (v.y - mu) * inv;
    float nz = (v.z - mu) * inv;
    float nw = (v.w - mu) * inv;

    float4 g1 = ((const float4*)gt)[t];
    float4 b1 = ((const float4*)bt)[t];
    float4 o1;
    o1.x = nx * g1.x + b1.x; o1.y = ny * g1.y + b1.y;
    o1.z = nz * g1.z + b1.z; o1.w = nw * g1.w + b1.w;
    ((float4*)(out + (size_t)row * DIM))[t] = o1;

    float4 g2 = ((const float4*)gi)[t];
    float4 b2 = ((const float4*)bi)[t];
    float4 o2;
    o2.x = nx * g2.x + b2.x; o2.y = ny * g2.y + b2.y;
    o2.z = nz * g2.z + b2.z; o2.w = nw * g2.w + b2.w;
    ((float4*)(out + ((size_t)(row + ROWS)) * DIM))[t] = o2;
}

// ============================================================================
// Shared GEMM core: mma.sync fp16 single-pass (BM=128, BN=64, BK=64, 256 thr)
// 8 warps 4x2, 32x32 warp tile (register-banking sweet spot).
// LAYOUT 0 (NT): B = [N,K] k-contiguous
// LAYOUT 1 (NN): B = [K,N] n-contiguous (ldmatrix.trans)
// EPI 0: fp32 C (alpha + bias)                      [Wo -> XO]
// EPI 1: fp16 C (alpha + bias)                      [projections]
// EPI 2: fp16 C = exp(min(alpha*acc,11))            [scores -> E]
// EPI 3: fp16 C = acc / rowsum(A)   (self-normalizing PV; rowsum from smem A)
// ============================================================================
template<int LAYOUT, int EPI>
__device__ __forceinline__ void gemm_core(
    const __half* __restrict__ A, const __half* __restrict__ B,
    const float* __restrict__ bias,
    float* __restrict__ Cf, __half* __restrict__ CH,
    int N, int K, float alpha, int m0, int n0, char* smemc)
{
    uint32_t base = smem_to_u32(smemc);
    int tid = threadIdx.x, wid = tid >> 5, lane = tid & 31;
    int NK = K / BK;

    auto stage_of = [&](int kt) -> uint32_t {
        int s = kt % STAGES;
        return base + (uint32_t)s * STB;
    };

    auto load_stage = [&](int kt) {
        uint32_t sb = stage_of(kt);
        int kb = kt * BK;
        // A: 128 rows x 128B, SW128 swizzle. 1024 slots, 4 per thread.
        #pragma unroll
        for (int i = 0; i < 4; i++) {
            int slot = tid + i * THREADS;
            int row = slot >> 3, unit = slot & 7;
            uint32_t off = (uint32_t)(row * 128 + unit * 16);
            off ^= (off >> 3) & 0x70;
            CP_A16(sb + ST_A + off, A + (size_t)(m0 + row) * K + kb + unit * 8);
        }
        if (LAYOUT == 0) {
            // B NT: 64 rows x 128B. 512 slots, 2 per thread.
            #pragma unroll
            for (int i = 0; i < 2; i++) {
                int slot = tid + i * THREADS;
                int row = slot >> 3, unit = slot & 7;
                uint32_t off = (uint32_t)(row * 128 + unit * 16);
                off ^= (off >> 3) & 0x70;
                CP_A16(sb + ST_B + off, B + (size_t)(n0 + row) * K + kb + unit * 8);
            }
        } else {
            // B NN: 64 k-rows x 128B (BN=64). 512 slots, 2 per thread.
            #pragma unroll
            for (int i = 0; i < 2; i++) {
                int slot = tid + i * THREADS;
                int row = slot >> 3, unit = slot & 7;
                uint32_t off = (uint32_t)(row * 128 + unit * 16);
                off ^= (off >> 3) & 0x70;
                CP_A16(sb + ST_B + off, B + (size_t)(kb + row) * N + n0 + unit * 8);
            }
        }
    };

    load_stage(0); CP_COMMIT();
    load_stage(1); CP_COMMIT();

    int wm = wid & 3, wn = wid >> 2;     // 4x2 warp grid, 32x32 warp tile
    float acc[2][4][4];
    #pragma unroll
    for (int a = 0; a < 2; a++)
        #pragma unroll
        for (int b = 0; b < 4; b++)
            #pragma unroll
            for (int c = 0; c < 4; c++) acc[a][b][c] = 0.0f;

    float psum = 0.0f;   // EPI 3: partial row sum of A (this thread's slice)

    for (int kt = 0; kt < NK; kt++) {
        if (kt + 2 < NK)      { load_stage(kt + 2); CP_COMMIT(); CP_WAIT(2); }
        else if (kt + 1 < NK) { CP_WAIT(1); }
        else                  { CP_WAIT(0); }
        __syncthreads();

        uint32_t sb = stage_of(kt);

        #pragma unroll
        for (int ks = 0; ks < 4; ks++) {
            int k0 = ks * 16;

            uint32_t ar[2][4];
            #pragma unroll
            for (int mt = 0; mt < 2; mt++) {
                int row = wm * 32 + mt * 16 + (lane & 15);
                uint32_t off = (uint32_t)(row * 128 + k0 * 2 + ((lane >> 4) << 4));
                off ^= (off >> 3) & 0x70;
                ldm_x4(ar[mt], sb + ST_A + off);
            }

            uint32_t br[4][2];
            if (LAYOUT == 0) {
                #pragma unroll
                for (int p = 0; p < 2; p++) {
                    int nrow = wn * 32 + p * 16 + (lane & 7) + 8 * ((lane >> 4) & 1);
                    uint32_t off = (uint32_t)(nrow * 128 + k0 * 2 + ((lane >> 3) & 1) * 16);
                    off ^= (off >> 3) & 0x70;
                    uint32_t r[4];
                    ldm_x4(r, sb + ST_B + off);
                    br[p*2][0] = r[0]; br[p*2][1] = r[1];
                    br[p*2+1][0] = r[2]; br[p*2+1][1] = r[3];
                }
            } else {
                #pragma unroll
                for (int p = 0; p < 2; p++) {
                    int krow = k0 + (lane & 7) + 8 * ((lane >> 3) & 1);
                    int ncol = wn * 32 + p * 16 + 8 * (lane >> 4);
                    uint32_t off = (uint32_t)(krow * 128 + ncol * 2);
                    off ^= (off >> 3) & 0x70;
                    uint32_t r[4];
                    ldm_x4_t(r, sb + ST_B + off);
                    br[p*2][0] = r[0]; br[p*2][1] = r[1];
                    br[p*2+1][0] = r[2]; br[p*2+1][1] = r[3];
                }
            }

            #pragma unroll
            for (int mt = 0; mt < 2; mt++)
                #pragma unroll
                for (int nt = 0; nt < 4; nt++)
                    mma_f16(acc[mt][nt], ar[mt], br[nt]);
        }

        if (EPI == 3) {
            // Accumulate row sums of the A tile (2 threads/row, 4x16B each).
            uint32_t sboff = (uint32_t)(kt % STAGES) * STB + ST_A;
            int row = tid >> 1;
            #pragma unroll
            for (int u = 0; u < 4; u++) {
                uint32_t off = (uint32_t)(row * 128 + ((tid & 1) * 4 + u) * 16);
                off ^= (off >> 3) & 0x70;
                uint4 v = *(const uint4*)(smemc + sboff + off);
                const __half2* h = (const __half2*)&v;
                #pragma unroll
                for (int j = 0; j < 4; j++) {
                    float2 f = __half22float2(h[j]);
                    psum += f.x + f.y;
                }
            }
        }
        __syncthreads();
    }

    // ---------------- epilogue ----------------
    float* rowsumSm = (float*)smemc;   // EPI 3 only; pipeline smem is free now
    if (EPI == 3) {
        psum += __shfl_xor_sync(0xffffffffu, psum, 1);
        if ((tid & 1) == 0) rowsumSm[tid >> 1] = psum;
        __syncthreads();
    }

    #pragma unroll
    for (int mt = 0; mt < 2; mt++) {
        int lr   = wm * 32 + mt * 16 + (lane >> 2);   // local row in [0,128)
        int mrow = m0 + lr;
        float rs0 = 1.0f, rs1 = 1.0f;
        if (EPI == 3) {
            rs0 = 1.0f / rowsumSm[lr];
            rs1 = 1.0f / rowsumSm[lr + 8];
        }
        #pragma unroll
        for (int nt = 0; nt < 4; nt++) {
            int n = n0 + wn * 32 + nt * 8 + (lane & 3) * 2;
            float c0, c1, c2, c3;
            if (EPI == 0 || EPI == 1) {
                float b0 = bias ? __ldg(&bias[n])     : 0.0f;
                float b1 = bias ? __ldg(&bias[n + 1]) : 0.0f;
                c0 = alpha * acc[mt][nt][0] + b0;
                c1 = alpha * acc[mt][nt][1] + b1;
                c2 = alpha * acc[mt][nt][2] + b0;
                c3 = alpha * acc[mt][nt][3] + b1;
            } else if (EPI == 2) {
                c0 = __expf(fminf(alpha * acc[mt][nt][0], 11.0f));
                c1 = __expf(fminf(alpha * acc[mt][nt][1], 11.0f));
                c2 = __expf(fminf(alpha * acc[mt][nt][2], 11.0f));
                c3 = __expf(fminf(alpha * acc[mt][nt][3], 11.0f));
            } else {  // EPI == 3
                c0 = acc[mt][nt][0] * rs0;
                c1 = acc[mt][nt][1] * rs0;
                c2 = acc[mt][nt][2] * rs1;
                c3 = acc[mt][nt][3] * rs1;
            }
            size_t o0 = (size_t)mrow * N + n;
            size_t o1 = (size_t)(mrow + 8) * N + n;
            if (EPI == 0) {
                *(float2*)(Cf + o0) = make_float2(c0, c1);
                *(float2*)(Cf + o1) = make_float2(c2, c3);
            } else {
                *(__half2*)(CH + o0) = __halves2half2(__float2half(c0), __float2half(c1));
                *(__half2*)(CH + o1) = __halves2half2(__float2half(c2), __float2half(c3));
            }
        }
    }
}

// Generic batched wrapper
template<int LAYOUT, int EPI>
__global__ void __launch_bounds__(THREADS, 2) mma_gemm_kernel(
    const __half* __restrict__ A, const __half* __restrict__ B,
    const float* __restrict__ bias,
    float* __restrict__ Cf, __half* __restrict__ CH,
    int N, int K, float alpha,
    long long sA, long long sB, long long sC)
{
    extern __shared__ char smem[];
    int z = blockIdx.z;
    gemm_core<LAYOUT, EPI>(
        A + (size_t)z * sA, B + (size_t)z * sB, bias,
        Cf ? Cf + (size_t)z * sC : nullptr,
        CH ? CH + (size_t)z * sC : nullptr,
        N, K, alpha, blockIdx.y * BM, blockIdx.x * BN, smem);
}

// Merged projection kernel: Q, Kt, Ki, Vt, Vi in one launch.
// grid = (8, 384): y<128 Q | y<192 Kt | y<256 Ki | y<320 Vt | y<384 Vi
__global__ void __launch_bounds__(THREADS, 2) proj_kernel(
    const __half* __restrict__ NORM, const __half* __restrict__ W,
    const float* __restrict__ bq, const float* __restrict__ bkt,
    const float* __restrict__ bki, const float* __restrict__ bvt,
    const float* __restrict__ bvi,
    __half* __restrict__ Q, __half* __restrict__ K, __half* __restrict__ V)
{
    extern __shared__ char smem[];
    const size_t WSZ = (size_t)DIM * DIM;
    int y = blockIdx.y;
    int mat, arow;
    __half* outp;
    const float* bias;
    if (y < 128)      { mat = 0; arow = y * 128;                outp = Q; bias = bq; }
    else if (y < 192) { mat = 1; arow = (y - 128) * 128;        outp = K; bias = bkt; }
    else if (y < 256) { mat = 3; arow = 8192 + (y - 192) * 128; outp = K; bias = bki; }
    else if (y < 320) { mat = 2; arow = (y - 256) * 128;        outp = V; bias = bvt; }
    else              { mat = 4; arow = 8192 + (y - 320) * 128; outp = V; bias = bvi; }

    gemm_core<0, 1>(
        NORM + (size_t)arow * DIM, W + (size_t)mat * WSZ, bias,
        nullptr, outp + (size_t)arow * DIM,
        DIM, DIM, 1.0f, 0, blockIdx.x * BN, smem);
}

// ============================================================================
// Host orchestration
// ============================================================================
extern "C" void kernel_launch(void* const* d_in, const int* in_sizes, int n_in,
                              void* d_out, int out_size)
{
    const float* text  = (const float*)d_in[0];
    const float* img   = (const float*)d_in[1];
    const float* ln_tg = (const float*)d_in[2];
    const float* ln_tb = (const float*)d_in[3];
    const float* ln_ig = (const float*)d_in[4];
    const float* ln_ib = (const float*)d_in[5];
    const float* Wq  = (const float*)d_in[6];  const float* bq  = (const float*)d_in[7];
    const float* Wkt = (const float*)d_in[8];  const float* bkt = (const float*)d_in[9];
    const float* Wvt = (const float*)d_in[10]; const float* bvt = (const float*)d_in[11];
    const float* Wki = (const float*)d_in[12]; const float* bki = (const float*)d_in[13];
    const float* Wvi = (const float*)d_in[14]; const float* bvi = (const float*)d_in[15];
    const float* Wo  = (const float*)d_in[16]; const float* bo  = (const float*)d_in[17];
    float* out = (float*)d_out;

    static bool attr_done = false;
    if (!attr_done) {
        cudaFuncSetAttribute(proj_kernel,          cudaFuncAttributeMaxDynamicSharedMemorySize, SMEM_DYN);
        cudaFuncSetAttribute(mma_gemm_kernel<0,0>, cudaFuncAttributeMaxDynamicSharedMemorySize, SMEM_DYN);
        cudaFuncSetAttribute(mma_gemm_kernel<0,2>, cudaFuncAttributeMaxDynamicSharedMemorySize, SMEM_DYN);
        cudaFuncSetAttribute(mma_gemm_kernel<1,3>, cudaFuncAttributeMaxDynamicSharedMemorySize, SMEM_DYN);
        attr_done = true;
    }

    void *pN, *pQ, *pK, *pV, *pE, *pX, *pW, *pXO;
    cudaGetSymbolAddress(&pN, g_norms);
    cudaGetSymbolAddress(&pQ, g_Q); cudaGetSymbolAddress(&pK, g_K); cudaGetSymbolAddress(&pV, g_V);
    cudaGetSymbolAddress(&pE, g_E); cudaGetSymbolAddress(&pX, g_X);
    cudaGetSymbolAddress(&pW, g_W); cudaGetSymbolAddress(&pXO, g_XO);

    __half* NORM = (__half*)pN;
    __half* Q = (__half*)pQ; __half* K = (__half*)pK; __half* V = (__half*)pV;
    __half* E = (__half*)pE; __half* X = (__half*)pX;
    __half* W = (__half*)pW;
    float* XO = (float*)pXO;

    const float scale = 0.04419417382415922f;  // 512^-0.5
    const size_t WSZ = (size_t)DIM * DIM;      // 262144

    // 1) input LN -> fp16 norms
    ln_in_kernel<<<ROWS, 128>>>(text, img, ln_tg, ln_tb, ln_ig, ln_ib, NORM);

    // 2) convert weights (order: q, kt, vt, ki, vi, o)
    convert_weights_kernel<<<dim3(1024, 6), 256>>>(Wq, Wkt, Wvt, Wki, Wvi, Wo, W);

    // 3) all projections, one launch
    proj_kernel<<<dim3(8, 384), THREADS, SMEM_DYN>>>(
        NORM, W, bq, bkt, bki, bvt, bvi, Q, K, V);

    // 4) E = exp(scale * Q @ K^T) (batched NT)
    mma_gemm_kernel<0,2><<<dim3(64, 32, NBAT), THREADS, SMEM_DYN>>>(
        Q, K, nullptr, nullptr, E,
        S_LEN, DIM, scale,
        (long long)S_LEN * DIM, (long long)S_LEN * DIM, (long long)S_LEN * S_LEN);

    // 5) X = (E @ V) / rowsum(E) (batched NN, self-normalizing)
    mma_gemm_kernel<1,3><<<dim3(8, 32, NBAT), THREADS, SMEM_DYN>>>(
        E, V, nullptr, nullptr, X,
        DIM, S_LEN, 1.0f,
        (long long)S_LEN * S_LEN, (long long)S_LEN * DIM, (long long)S_LEN * DIM);

    // 6) XO = X @ Wo^T + bo (NT, fp32 out)
    mma_gemm_kernel<0,0><<<dim3(8, 128, 1), THREADS, SMEM_DYN>>>(
        X, W + 5*WSZ, bo, XO, nullptr,
        DIM, DIM, 1.0f, 0, 0, 0);

    // 7) final dual LayerNorm (one block per XO row, both outputs)
    ln_out_dual_kernel<<<ROWS, 128>>>(XO, ln_tg, ln_tb, ln_ig, ln_ib, out);
}